// round 13
// baseline (speedup 1.0000x reference)
#include <cuda_runtime.h>
#include <cuda_bf16.h>
#include <cstdint>
#include <cstring>

static constexpr int HID  = 128;
static constexpr int MAXN = 50000;
static constexpr int MAXE = 500000;

// Scratch (device globals: no allocation allowed in kernel_launch)
__device__ int   g_cnt[MAXN];
__device__ int   g_cur[MAXN];
__device__ int   g_row[MAXN + 1];
__device__ int   g_bsum[256];
__device__ int   g_eidx[MAXE];
__device__ float g_agg[(long long)MAXN * HID];
__device__ float g_h1 [(long long)MAXN * HID];
__device__ float g_h2 [(long long)MAXN * HID];
// Split-bf16 weights, n-major [OUTC][256] (k: 0-127 = Wl, 128-255 = Wr).
// Layer offsets (elems): L1 @ 0, L2 @ 32768, L3 @ 65536.
__device__ __nv_bfloat16 g_whi[81920];
__device__ __nv_bfloat16 g_wlo[81920];

// ======================= CSR construction =======================

__global__ void hist_kernel(const int* __restrict__ dst, int E) {
    int i = blockIdx.x * blockDim.x + threadIdx.x;
    int e = i * 2;
    if (e + 1 < E) {
        int2 d = *(const int2*)(dst + e);
        atomicAdd(&g_cnt[d.x], 1);
        atomicAdd(&g_cnt[d.y], 1);
    } else if (e < E) {
        atomicAdd(&g_cnt[dst[e]], 1);
    }
}

// Per-block exclusive scan + block totals.
__global__ void scan_blk(int N) {
    __shared__ int sh[256];
    const int t = threadIdx.x;
    const int i = blockIdx.x * 256 + t;
    int v = (i < N) ? g_cnt[i] : 0;
    sh[t] = v;
    __syncthreads();
    for (int off = 1; off < 256; off <<= 1) {
        int u = (t >= off) ? sh[t - off] : 0;
        __syncthreads();
        sh[t] += u;
        __syncthreads();
    }
    if (i < N) g_row[i] = sh[t] - v;          // exclusive within block
    if (t == 255) g_bsum[blockIdx.x] = sh[255];
}

// Adds prefix of g_bsum (computed inline) and initializes cursors.
__global__ void scan_add(int N, int E) {
    __shared__ int s_off;
    const int t = threadIdx.x;
    // reduce g_bsum[0 .. blockIdx.x) cooperatively (<= 256 entries)
    int v = (t < blockIdx.x) ? g_bsum[t] : 0;
#pragma unroll
    for (int o = 16; o > 0; o >>= 1)
        v += __shfl_down_sync(0xFFFFFFFF, v, o);
    __shared__ int wsum[8];
    if ((t & 31) == 0) wsum[t >> 5] = v;
    __syncthreads();
    if (t == 0) {
        int s = 0;
#pragma unroll
        for (int w = 0; w < 8; w++) s += wsum[w];
        s_off = s;
    }
    __syncthreads();
    int i = blockIdx.x * 256 + t;
    if (i < N) {
        int r = g_row[i] + s_off;
        g_row[i] = r;
        g_cur[i] = r;                          // fill cursors start at row base
    }
    if (i == 0) g_row[N] = E;
}

__global__ void fill_kernel(const int* __restrict__ src,
                            const int* __restrict__ dst, int E) {
    int e = blockIdx.x * blockDim.x + threadIdx.x;
    if (e < E) {
        int pos = atomicAdd(&g_cur[dst[e]], 1);
        g_eidx[pos] = src[e];
    }
}

// ======================= Mean aggregation (warp-per-node gather, unroll-4) =======================

__global__ __launch_bounds__(256)
void csr_aggregate(const float* __restrict__ X, float* __restrict__ AGG, int N) {
    int w = (blockIdx.x * blockDim.x + threadIdx.x) >> 5;
    if (w >= N) return;
    const int lane = threadIdx.x & 31;
    const int s0 = g_row[w];
    const int s1 = g_row[w + 1];

    float4 a0 = make_float4(0.f, 0.f, 0.f, 0.f);
    float4 a1 = a0, a2 = a0, a3 = a0;
    int i = s0;
    for (; i + 3 < s1; i += 4) {
        int n0 = g_eidx[i];
        int n1 = g_eidx[i + 1];
        int n2 = g_eidx[i + 2];
        int n3 = g_eidx[i + 3];
        float4 v0 = ((const float4*)(X + (long long)n0 * HID))[lane];
        float4 v1 = ((const float4*)(X + (long long)n1 * HID))[lane];
        float4 v2 = ((const float4*)(X + (long long)n2 * HID))[lane];
        float4 v3 = ((const float4*)(X + (long long)n3 * HID))[lane];
        a0.x += v0.x; a0.y += v0.y; a0.z += v0.z; a0.w += v0.w;
        a1.x += v1.x; a1.y += v1.y; a1.z += v1.z; a1.w += v1.w;
        a2.x += v2.x; a2.y += v2.y; a2.z += v2.z; a2.w += v2.w;
        a3.x += v3.x; a3.y += v3.y; a3.z += v3.z; a3.w += v3.w;
    }
    for (; i < s1; i++) {
        int n0 = g_eidx[i];
        float4 v0 = ((const float4*)(X + (long long)n0 * HID))[lane];
        a0.x += v0.x; a0.y += v0.y; a0.z += v0.z; a0.w += v0.w;
    }
    float inv = 1.0f / (float)max(s1 - s0, 1);
    float4 o;
    o.x = (a0.x + a1.x + a2.x + a3.x) * inv;
    o.y = (a0.y + a1.y + a2.y + a3.y) * inv;
    o.z = (a0.z + a1.z + a2.z + a3.z) * inv;
    o.w = (a0.w + a1.w + a2.w + a3.w) * inv;
    ((float4*)(AGG + (long long)w * HID))[lane] = o;
}

// ======================= Weight prep (all 3 layers, one kernel) =======================

__device__ __forceinline__ void split_bf(float x, __nv_bfloat16& h, __nv_bfloat16& l) {
    h = __float2bfloat16(x);
    l = __float2bfloat16(x - __bfloat162float(h));
}

__global__ void prep_w_all(const float* __restrict__ W1l, const float* __restrict__ W1r,
                           const float* __restrict__ W2l, const float* __restrict__ W2r,
                           const float* __restrict__ W3l, const float* __restrict__ W3r) {
    int i = blockIdx.x * blockDim.x + threadIdx.x;
    if (i >= 81920) return;
    const float *Wl, *Wr;
    int outc, base;
    if (i < 32768)      { Wl = W1l; Wr = W1r; outc = 128; base = 0; }
    else if (i < 65536) { Wl = W2l; Wr = W2r; outc = 128; base = 32768; }
    else                { Wl = W3l; Wr = W3r; outc = 64;  base = 65536; }
    int li = i - base;
    int n = li >> 8;
    int k = li & 255;
    float v = (k < 128) ? Wl[k * outc + n] : Wr[(k - 128) * outc + n];
    __nv_bfloat16 h, l;
    split_bf(v, h, l);
    g_whi[i] = h;
    g_wlo[i] = l;
}

// ======================= bf16 mma.sync SAGE layer =======================
// Y = act(agg @ Wl + x @ Wr + b), D = Ah*Bh + Ah*Bl + Al*Bh (fp32 accum).
// Two K-phases (phase 0: agg/Wl, phase 1: x/Wr); accumulators persist.
// CTA: 64-node tile x OUTC, 256 threads (2M x 4N warp grid), 2 CTAs/SM.

static constexpr int ASTR  = 136;                 // elems; 272B row stride (4-bank shift, conflict-free)
static constexpr int A_BYT = 64 * ASTR * 2;       // 17408

__device__ __forceinline__ void ldmA(uint32_t a[4], uint32_t addr) {
    asm volatile("ldmatrix.sync.aligned.m8n8.x4.shared.b16 {%0,%1,%2,%3}, [%4];"
                 : "=r"(a[0]), "=r"(a[1]), "=r"(a[2]), "=r"(a[3]) : "r"(addr));
}

__device__ __forceinline__ void mma16816(float c[4], const uint32_t a[4], const uint32_t b[2]) {
    asm volatile(
        "mma.sync.aligned.m16n8k16.row.col.f32.bf16.bf16.f32 "
        "{%0,%1,%2,%3}, {%4,%5,%6,%7}, {%8,%9}, {%0,%1,%2,%3};"
        : "+f"(c[0]), "+f"(c[1]), "+f"(c[2]), "+f"(c[3])
        : "r"(a[0]), "r"(a[1]), "r"(a[2]), "r"(a[3]), "r"(b[0]), "r"(b[1]));
}

__device__ __forceinline__ uint32_t smem_u32(const void* p) {
    uint32_t a;
    asm("{ .reg .u64 t; cvta.to.shared.u64 t, %1; cvt.u32.u64 %0, t; }"
        : "=r"(a) : "l"(p));
    return a;
}

template<int OUTC, bool RELU>
__global__ __launch_bounds__(256, 2)
void sage_mma(const float* __restrict__ X, const float* __restrict__ AGG,
              const float* __restrict__ bias, float* __restrict__ Y,
              int N, int wOff) {
    extern __shared__ char smem[];
    constexpr int OFF_AH = 0;
    constexpr int OFF_AL = A_BYT;
    constexpr int OFF_BH = 2 * A_BYT;
    constexpr int B_BYT  = OUTC * ASTR * 2;
    constexpr int OFF_BL = OFF_BH + B_BYT;

    const int t = threadIdx.x;
    const int wid = t >> 5;
    const int lane = t & 31;
    const int node0 = blockIdx.x * 64;

    const int warp_m = wid >> 2;
    const int warp_n = wid & 3;
    constexpr int WN = OUTC / 4;
    constexpr int NB = WN / 8;

    const int tid4 = lane & 3;
    const int grp  = lane >> 2;
    const int arow_in = lane & 15;
    const int acol    = (lane >> 4) * 8;

    float acc[2][NB][4];
#pragma unroll
    for (int m = 0; m < 2; m++)
#pragma unroll
        for (int nb = 0; nb < NB; nb++)
#pragma unroll
            for (int j = 0; j < 4; j++) acc[m][nb][j] = 0.f;

    const uint32_t sbase = smem_u32(smem);

#pragma unroll 1
    for (int p = 0; p < 2; p++) {
        const float* SRC = (p == 0) ? AGG : X;

        // ---- Stage A for this phase: 64 rows x 128 k, split hi/lo ----
        for (int i = t; i < 64 * 32; i += 256) {
            int row = i >> 5;
            int k = (i & 31) * 4;
            int node = node0 + row;
            float4 v = make_float4(0.f, 0.f, 0.f, 0.f);
            if (node < N)
                v = ((const float4*)(SRC + (long long)node * HID))[k >> 2];
            __nv_bfloat16 h0, h1, h2, h3, l0, l1, l2, l3;
            split_bf(v.x, h0, l0); split_bf(v.y, h1, l1);
            split_bf(v.z, h2, l2); split_bf(v.w, h3, l3);
            __nv_bfloat162 hA(h0, h1), hB(h2, h3), lA(l0, l1), lB(l2, l3);
            uint2 hp, lp;
            memcpy(&hp.x, &hA, 4); memcpy(&hp.y, &hB, 4);
            memcpy(&lp.x, &lA, 4); memcpy(&lp.y, &lB, 4);
            uint32_t off = (uint32_t)(row * (ASTR * 2) + k * 2);
            *(uint2*)(smem + OFF_AH + off) = hp;
            *(uint2*)(smem + OFF_AL + off) = lp;
        }

        // ---- Stage B for this phase: OUTC rows x 128 k from prepped weights ----
        for (int i = t; i < OUTC * 16; i += 256) {
            int n = i >> 4;
            int c = i & 15;                       // 16B chunk (8 bf16)
            int gsrc = (wOff + n * 256 + p * 128) / 8 + c;
            uint32_t off = (uint32_t)(n * (ASTR * 2) + c * 16);
            *(uint4*)(smem + OFF_BH + off) = ((const uint4*)g_whi)[gsrc];
            *(uint4*)(smem + OFF_BL + off) = ((const uint4*)g_wlo)[gsrc];
        }
        __syncthreads();

        // ---- 3-term MMA over this phase's K=128 ----
#pragma unroll 1
        for (int term = 0; term < 3; term++) {
            const uint32_t Abase = sbase + ((term == 2) ? OFF_AL : OFF_AH);
            const uint32_t Bbase = sbase + ((term == 1) ? OFF_BL : OFF_BH);
            const uint32_t aAddr0 = Abase + (uint32_t)((warp_m * 32 + arow_in) * (ASTR * 2));
            const uint32_t bAddr0 = Bbase + (uint32_t)((warp_n * WN + grp) * (ASTR * 2));
#pragma unroll
            for (int k0 = 0; k0 < 128; k0 += 16) {
                uint32_t a[2][4];
#pragma unroll
                for (int m = 0; m < 2; m++)
                    ldmA(a[m], aAddr0 + (uint32_t)(m * 16 * (ASTR * 2) + (k0 + acol) * 2));
                uint32_t bf[NB][2];
#pragma unroll
                for (int nb = 0; nb < NB; nb++) {
                    uint32_t ba = bAddr0 + (uint32_t)(nb * 8 * (ASTR * 2) + (k0 + tid4 * 2) * 2);
                    asm volatile("ld.shared.b32 %0, [%1];" : "=r"(bf[nb][0]) : "r"(ba));
                    asm volatile("ld.shared.b32 %0, [%1];" : "=r"(bf[nb][1]) : "r"(ba + 16));
                }
#pragma unroll
                for (int m = 0; m < 2; m++)
#pragma unroll
                    for (int nb = 0; nb < NB; nb++)
                        mma16816(acc[m][nb], a[m], bf[nb]);
            }
        }
        __syncthreads();   // all warps done reading smem before next phase restages
    }

    // ---- Epilogue: bias + activation, direct global store ----
#pragma unroll
    for (int nb = 0; nb < NB; nb++) {
        const int col0 = warp_n * WN + nb * 8 + tid4 * 2;
        const float bx = __ldg(bias + col0);
        const float by = __ldg(bias + col0 + 1);
#pragma unroll
        for (int m = 0; m < 2; m++) {
            int r0 = node0 + warp_m * 32 + m * 16 + grp;
#pragma unroll
            for (int h = 0; h < 2; h++) {
                int node = r0 + h * 8;
                if (node < N) {
                    float2 o;
                    o.x = acc[m][nb][h * 2 + 0] + bx;
                    o.y = acc[m][nb][h * 2 + 1] + by;
                    if (RELU) { o.x = fmaxf(o.x, 0.f); o.y = fmaxf(o.y, 0.f); }
                    *(float2*)(Y + (long long)node * OUTC + col0) = o;
                }
            }
        }
    }
}

// ======================= Driver =======================

template<int OUTC, bool RELU>
static void run_layer(const float* X, const float* b, float* Y, int N,
                      float* p_agg, int wOff) {
    csr_aggregate<<<(N * 32 + 255) / 256, 256>>>(X, p_agg, N);
    size_t smem = 2 * A_BYT + 2 * (size_t)OUTC * ASTR * 2;
    sage_mma<OUTC, RELU><<<(N + 63) / 64, 256, smem>>>(X, p_agg, b, Y, N, wOff);
}

extern "C" void kernel_launch(void* const* d_in, const int* in_sizes, int n_in,
                              void* d_out, int out_size) {
    const float* x   = (const float*)d_in[0];
    const int*   ei  = (const int*)  d_in[1];
    const float* W1l = (const float*)d_in[2];
    const float* W1r = (const float*)d_in[3];
    const float* b1  = (const float*)d_in[4];
    const float* W2l = (const float*)d_in[5];
    const float* W2r = (const float*)d_in[6];
    const float* b2  = (const float*)d_in[7];
    const float* W3l = (const float*)d_in[8];
    const float* W3r = (const float*)d_in[9];
    const float* b3  = (const float*)d_in[10];
    float* out = (float*)d_out;

    const int N = in_sizes[0] / HID;   // 50000
    const int E = in_sizes[1] / 2;     // 500000
    const int* src = ei;
    const int* dst = ei + E;

    float *p_agg, *p_h1, *p_h2;
    int *p_cnt;
    cudaGetSymbolAddress((void**)&p_agg, g_agg);
    cudaGetSymbolAddress((void**)&p_h1,  g_h1);
    cudaGetSymbolAddress((void**)&p_h2,  g_h2);
    cudaGetSymbolAddress((void**)&p_cnt, g_cnt);

    cudaFuncSetAttribute(sage_mma<128, true>,
                         cudaFuncAttributeMaxDynamicSharedMemorySize,
                         2 * A_BYT + 2 * 128 * ASTR * 2);
    cudaFuncSetAttribute(sage_mma<64, false>,
                         cudaFuncAttributeMaxDynamicSharedMemorySize,
                         2 * A_BYT + 2 * 64 * ASTR * 2);

    // Weight prep (independent of CSR build)
    prep_w_all<<<(81920 + 255) / 256, 256>>>(W1l, W1r, W2l, W2r, W3l, W3r);

    // CSR build: hist -> per-block scan -> add (inline block-offset reduce) -> fill
    const int NB_BLK = (N + 255) / 256;   // 196 <= 256
    cudaMemsetAsync(p_cnt, 0, (size_t)N * sizeof(int));
    hist_kernel<<<(E / 2 + 255) / 256, 256>>>(dst, E);
    scan_blk<<<NB_BLK, 256>>>(N);
    scan_add<<<NB_BLK, 256>>>(N, E);
    fill_kernel<<<(E + 255) / 256, 256>>>(src, dst, E);

    run_layer<128, true >(x,    b1, p_h1, N, p_agg, 0);
    run_layer<128, true >(p_h1, b2, p_h2, N, p_agg, 32768);
    run_layer<64,  false>(p_h2, b3, out,  N, p_agg, 65536);
}

// round 14
// speedup vs baseline: 1.4215x; 1.4215x over previous
#include <cuda_runtime.h>
#include <cuda_bf16.h>
#include <cstdint>
#include <cstring>

static constexpr int HID  = 128;
static constexpr int MAXN = 50000;
static constexpr int MAXE = 500000;

// Scratch (device globals: no allocation allowed in kernel_launch)
__device__ int   g_cnt[MAXN];
__device__ int   g_cur[MAXN];
__device__ int   g_row[MAXN + 1];
__device__ int   g_bsum[256];
__device__ int   g_eidx[MAXE];
__device__ float g_agg[(long long)MAXN * HID];
__device__ float g_h1 [(long long)MAXN * HID];
__device__ float g_h2 [(long long)MAXN * HID];
// Split-bf16 weights, n-major [OUTC][256] (k: 0-127 = Wl, 128-255 = Wr).
// Layer offsets (elems): L1 @ 0, L2 @ 32768, L3 @ 65536.
__device__ __nv_bfloat16 g_whi[81920];
__device__ __nv_bfloat16 g_wlo[81920];

// ======================= CSR construction =======================

__global__ void hist_kernel(const int* __restrict__ dst, int E) {
    int e = blockIdx.x * blockDim.x + threadIdx.x;
    if (e < E) atomicAdd(&g_cnt[dst[e]], 1);
}

// Hierarchical scan: per-block exclusive scan + block totals.
__global__ void scan_blk(int N) {
    __shared__ int sh[256];
    const int t = threadIdx.x;
    const int i = blockIdx.x * 256 + t;
    int v = (i < N) ? g_cnt[i] : 0;
    sh[t] = v;
    __syncthreads();
    for (int off = 1; off < 256; off <<= 1) {
        int u = (t >= off) ? sh[t - off] : 0;
        __syncthreads();
        sh[t] += u;
        __syncthreads();
    }
    if (i < N) g_row[i] = sh[t] - v;          // exclusive within block
    if (t == 255) g_bsum[blockIdx.x] = sh[255];
}

__global__ void scan_bsum(int B) {
    __shared__ int sh[256];
    const int t = threadIdx.x;
    int v = (t < B) ? g_bsum[t] : 0;
    sh[t] = v;
    __syncthreads();
    for (int off = 1; off < 256; off <<= 1) {
        int u = (t >= off) ? sh[t - off] : 0;
        __syncthreads();
        sh[t] += u;
        __syncthreads();
    }
    if (t < B) g_bsum[t] = sh[t] - v;          // exclusive block offsets
}

__global__ void scan_add(int N, int E) {
    int i = blockIdx.x * 256 + threadIdx.x;
    if (i < N) {
        int r = g_row[i] + g_bsum[blockIdx.x];
        g_row[i] = r;
        g_cur[i] = r;                          // fill cursors start at row base
    }
    if (i == 0) g_row[N] = E;
}

__global__ void fill_kernel(const int* __restrict__ src,
                            const int* __restrict__ dst, int E) {
    int e = blockIdx.x * blockDim.x + threadIdx.x;
    if (e < E) {
        int pos = atomicAdd(&g_cur[dst[e]], 1);
        g_eidx[pos] = src[e];
    }
}

// ======================= Mean aggregation (warp-per-node gather) =======================

__global__ __launch_bounds__(256)
void csr_aggregate(const float* __restrict__ X, float* __restrict__ AGG, int N) {
    int w = (blockIdx.x * blockDim.x + threadIdx.x) >> 5;
    if (w >= N) return;
    const int lane = threadIdx.x & 31;
    const int s0 = g_row[w];
    const int s1 = g_row[w + 1];

    float4 a0 = make_float4(0.f, 0.f, 0.f, 0.f);
    float4 a1 = a0;
    int i = s0;
    for (; i + 1 < s1; i += 2) {
        int n0 = g_eidx[i];
        int n1 = g_eidx[i + 1];
        float4 v0 = ((const float4*)(X + (long long)n0 * HID))[lane];
        float4 v1 = ((const float4*)(X + (long long)n1 * HID))[lane];
        a0.x += v0.x; a0.y += v0.y; a0.z += v0.z; a0.w += v0.w;
        a1.x += v1.x; a1.y += v1.y; a1.z += v1.z; a1.w += v1.w;
    }
    if (i < s1) {
        int n0 = g_eidx[i];
        float4 v0 = ((const float4*)(X + (long long)n0 * HID))[lane];
        a0.x += v0.x; a0.y += v0.y; a0.z += v0.z; a0.w += v0.w;
    }
    float inv = 1.0f / (float)max(s1 - s0, 1);
    float4 o;
    o.x = (a0.x + a1.x) * inv;
    o.y = (a0.y + a1.y) * inv;
    o.z = (a0.z + a1.z) * inv;
    o.w = (a0.w + a1.w) * inv;
    ((float4*)(AGG + (long long)w * HID))[lane] = o;
}

// ======================= Weight prep (all 3 layers, one kernel) =======================

__device__ __forceinline__ void split_bf(float x, __nv_bfloat16& h, __nv_bfloat16& l) {
    h = __float2bfloat16(x);
    l = __float2bfloat16(x - __bfloat162float(h));
}

__global__ void prep_w_all(const float* __restrict__ W1l, const float* __restrict__ W1r,
                           const float* __restrict__ W2l, const float* __restrict__ W2r,
                           const float* __restrict__ W3l, const float* __restrict__ W3r) {
    int i = blockIdx.x * blockDim.x + threadIdx.x;
    if (i >= 81920) return;
    const float *Wl, *Wr;
    int outc, base;
    if (i < 32768)      { Wl = W1l; Wr = W1r; outc = 128; base = 0; }
    else if (i < 65536) { Wl = W2l; Wr = W2r; outc = 128; base = 32768; }
    else                { Wl = W3l; Wr = W3r; outc = 64;  base = 65536; }
    int li = i - base;
    int n = li >> 8;
    int k = li & 255;
    float v = (k < 128) ? Wl[k * outc + n] : Wr[(k - 128) * outc + n];
    __nv_bfloat16 h, l;
    split_bf(v, h, l);
    g_whi[i] = h;
    g_wlo[i] = l;
}

// ======================= bf16 mma.sync SAGE layer =======================
// Y = act(agg @ Wl + x @ Wr + b), D = Ah*Bh + Ah*Bl + Al*Bh (fp32 accum).
// Two K-phases (phase 0: agg/Wl, phase 1: x/Wr); accumulators persist.
// CTA: 64-node tile x OUTC, 256 threads (2M x 4N warp grid), 2 CTAs/SM.

static constexpr int ASTR  = 136;                 // elems; 272B row stride (4-bank shift, conflict-free)
static constexpr int A_BYT = 64 * ASTR * 2;       // 17408

__device__ __forceinline__ void ldmA(uint32_t a[4], uint32_t addr) {
    asm volatile("ldmatrix.sync.aligned.m8n8.x4.shared.b16 {%0,%1,%2,%3}, [%4];"
                 : "=r"(a[0]), "=r"(a[1]), "=r"(a[2]), "=r"(a[3]) : "r"(addr));
}

__device__ __forceinline__ void mma16816(float c[4], const uint32_t a[4], const uint32_t b[2]) {
    asm volatile(
        "mma.sync.aligned.m16n8k16.row.col.f32.bf16.bf16.f32 "
        "{%0,%1,%2,%3}, {%4,%5,%6,%7}, {%8,%9}, {%0,%1,%2,%3};"
        : "+f"(c[0]), "+f"(c[1]), "+f"(c[2]), "+f"(c[3])
        : "r"(a[0]), "r"(a[1]), "r"(a[2]), "r"(a[3]), "r"(b[0]), "r"(b[1]));
}

__device__ __forceinline__ uint32_t smem_u32(const void* p) {
    uint32_t a;
    asm("{ .reg .u64 t; cvta.to.shared.u64 t, %1; cvt.u32.u64 %0, t; }"
        : "=r"(a) : "l"(p));
    return a;
}

template<int OUTC, bool RELU>
__global__ __launch_bounds__(256, 2)
void sage_mma(const float* __restrict__ X, const float* __restrict__ AGG,
              const float* __restrict__ bias, float* __restrict__ Y,
              int N, int wOff) {
    extern __shared__ char smem[];
    constexpr int OFF_AH = 0;
    constexpr int OFF_AL = A_BYT;
    constexpr int OFF_BH = 2 * A_BYT;
    constexpr int B_BYT  = OUTC * ASTR * 2;
    constexpr int OFF_BL = OFF_BH + B_BYT;

    const int t = threadIdx.x;
    const int wid = t >> 5;
    const int lane = t & 31;
    const int node0 = blockIdx.x * 64;

    const int warp_m = wid >> 2;
    const int warp_n = wid & 3;
    constexpr int WN = OUTC / 4;
    constexpr int NB = WN / 8;

    const int tid4 = lane & 3;
    const int grp  = lane >> 2;
    const int arow_in = lane & 15;
    const int acol    = (lane >> 4) * 8;

    float acc[2][NB][4];
#pragma unroll
    for (int m = 0; m < 2; m++)
#pragma unroll
        for (int nb = 0; nb < NB; nb++)
#pragma unroll
            for (int j = 0; j < 4; j++) acc[m][nb][j] = 0.f;

    const uint32_t sbase = smem_u32(smem);

#pragma unroll 1
    for (int p = 0; p < 2; p++) {
        const float* SRC = (p == 0) ? AGG : X;

        // ---- Stage A for this phase: 64 rows x 128 k, split hi/lo ----
        for (int i = t; i < 64 * 32; i += 256) {
            int row = i >> 5;
            int k = (i & 31) * 4;
            int node = node0 + row;
            float4 v = make_float4(0.f, 0.f, 0.f, 0.f);
            if (node < N)
                v = ((const float4*)(SRC + (long long)node * HID))[k >> 2];
            __nv_bfloat16 h0, h1, h2, h3, l0, l1, l2, l3;
            split_bf(v.x, h0, l0); split_bf(v.y, h1, l1);
            split_bf(v.z, h2, l2); split_bf(v.w, h3, l3);
            __nv_bfloat162 hA(h0, h1), hB(h2, h3), lA(l0, l1), lB(l2, l3);
            uint2 hp, lp;
            memcpy(&hp.x, &hA, 4); memcpy(&hp.y, &hB, 4);
            memcpy(&lp.x, &lA, 4); memcpy(&lp.y, &lB, 4);
            uint32_t off = (uint32_t)(row * (ASTR * 2) + k * 2);
            *(uint2*)(smem + OFF_AH + off) = hp;
            *(uint2*)(smem + OFF_AL + off) = lp;
        }

        // ---- Stage B for this phase: OUTC rows x 128 k from prepped weights ----
        for (int i = t; i < OUTC * 16; i += 256) {
            int n = i >> 4;
            int c = i & 15;                       // 16B chunk (8 bf16)
            int gsrc = (wOff + n * 256 + p * 128) / 8 + c;
            uint32_t off = (uint32_t)(n * (ASTR * 2) + c * 16);
            *(uint4*)(smem + OFF_BH + off) = ((const uint4*)g_whi)[gsrc];
            *(uint4*)(smem + OFF_BL + off) = ((const uint4*)g_wlo)[gsrc];
        }
        __syncthreads();

        // ---- 3-term MMA over this phase's K=128 ----
#pragma unroll 1
        for (int term = 0; term < 3; term++) {
            const uint32_t Abase = sbase + ((term == 2) ? OFF_AL : OFF_AH);
            const uint32_t Bbase = sbase + ((term == 1) ? OFF_BL : OFF_BH);
            const uint32_t aAddr0 = Abase + (uint32_t)((warp_m * 32 + arow_in) * (ASTR * 2));
            const uint32_t bAddr0 = Bbase + (uint32_t)((warp_n * WN + grp) * (ASTR * 2));
#pragma unroll
            for (int k0 = 0; k0 < 128; k0 += 16) {
                uint32_t a[2][4];
#pragma unroll
                for (int m = 0; m < 2; m++)
                    ldmA(a[m], aAddr0 + (uint32_t)(m * 16 * (ASTR * 2) + (k0 + acol) * 2));
                uint32_t bf[NB][2];
#pragma unroll
                for (int nb = 0; nb < NB; nb++) {
                    uint32_t ba = bAddr0 + (uint32_t)(nb * 8 * (ASTR * 2) + (k0 + tid4 * 2) * 2);
                    asm volatile("ld.shared.b32 %0, [%1];" : "=r"(bf[nb][0]) : "r"(ba));
                    asm volatile("ld.shared.b32 %0, [%1];" : "=r"(bf[nb][1]) : "r"(ba + 16));
                }
#pragma unroll
                for (int m = 0; m < 2; m++)
#pragma unroll
                    for (int nb = 0; nb < NB; nb++)
                        mma16816(acc[m][nb], a[m], bf[nb]);
            }
        }
        __syncthreads();   // all warps done reading smem before next phase restages
    }

    // ---- Epilogue: bias + activation, direct global store ----
#pragma unroll
    for (int nb = 0; nb < NB; nb++) {
        const int col0 = warp_n * WN + nb * 8 + tid4 * 2;
        const float bx = __ldg(bias + col0);
        const float by = __ldg(bias + col0 + 1);
#pragma unroll
        for (int m = 0; m < 2; m++) {
            int r0 = node0 + warp_m * 32 + m * 16 + grp;
#pragma unroll
            for (int h = 0; h < 2; h++) {
                int node = r0 + h * 8;
                if (node < N) {
                    float2 o;
                    o.x = acc[m][nb][h * 2 + 0] + bx;
                    o.y = acc[m][nb][h * 2 + 1] + by;
                    if (RELU) { o.x = fmaxf(o.x, 0.f); o.y = fmaxf(o.y, 0.f); }
                    *(float2*)(Y + (long long)node * OUTC + col0) = o;
                }
            }
        }
    }
}

// ======================= Driver =======================

template<int OUTC, bool RELU>
static void run_layer(const float* X, const float* b, float* Y, int N,
                      float* p_agg, int wOff) {
    csr_aggregate<<<(N * 32 + 255) / 256, 256>>>(X, p_agg, N);
    size_t smem = 2 * A_BYT + 2 * (size_t)OUTC * ASTR * 2;
    sage_mma<OUTC, RELU><<<(N + 63) / 64, 256, smem>>>(X, p_agg, b, Y, N, wOff);
}

extern "C" void kernel_launch(void* const* d_in, const int* in_sizes, int n_in,
                              void* d_out, int out_size) {
    const float* x   = (const float*)d_in[0];
    const int*   ei  = (const int*)  d_in[1];
    const float* W1l = (const float*)d_in[2];
    const float* W1r = (const float*)d_in[3];
    const float* b1  = (const float*)d_in[4];
    const float* W2l = (const float*)d_in[5];
    const float* W2r = (const float*)d_in[6];
    const float* b2  = (const float*)d_in[7];
    const float* W3l = (const float*)d_in[8];
    const float* W3r = (const float*)d_in[9];
    const float* b3  = (const float*)d_in[10];
    float* out = (float*)d_out;

    const int N = in_sizes[0] / HID;   // 50000
    const int E = in_sizes[1] / 2;     // 500000
    const int* src = ei;
    const int* dst = ei + E;

    float *p_agg, *p_h1, *p_h2;
    int *p_cnt;
    cudaGetSymbolAddress((void**)&p_agg, g_agg);
    cudaGetSymbolAddress((void**)&p_h1,  g_h1);
    cudaGetSymbolAddress((void**)&p_h2,  g_h2);
    cudaGetSymbolAddress((void**)&p_cnt, g_cnt);

    cudaFuncSetAttribute(sage_mma<128, true>,
                         cudaFuncAttributeMaxDynamicSharedMemorySize,
                         2 * A_BYT + 2 * 128 * ASTR * 2);
    cudaFuncSetAttribute(sage_mma<64, false>,
                         cudaFuncAttributeMaxDynamicSharedMemorySize,
                         2 * A_BYT + 2 * 64 * ASTR * 2);

    // Weight prep (independent of CSR build)
    prep_w_all<<<(81920 + 255) / 256, 256>>>(W1l, W1r, W2l, W2r, W3l, W3r);

    // CSR build: memset -> hist -> scan(3) -> fill
    const int NB_BLK = (N + 255) / 256;   // 196 <= 256
    cudaMemsetAsync(p_cnt, 0, (size_t)N * sizeof(int));
    hist_kernel<<<(E + 255) / 256, 256>>>(dst, E);
    scan_blk<<<NB_BLK, 256>>>(N);
    scan_bsum<<<1, 256>>>(NB_BLK);
    scan_add<<<NB_BLK, 256>>>(N, E);
    fill_kernel<<<(E + 255) / 256, 256>>>(src, dst, E);

    run_layer<128, true >(x,    b1, p_h1, N, p_agg, 0);
    run_layer<128, true >(p_h1, b2, p_h2, N, p_agg, 32768);
    run_layer<64,  false>(p_h2, b3, out,  N, p_agg, 65536);
}